// round 5
// baseline (speedup 1.0000x reference)
#include <cuda_runtime.h>
#include <cstdint>

typedef unsigned long long ull;

#define KKn  9
#define Bn   8
#define Cn   256
#define Hn   96
#define Wn   96
#define On   256
#define HWn  (Hn*Wn)          // 9216
#define KDIM (Cn*KKn)         // 2304

// ---- main kernel tiling ----
#define NT   512              // threads per block
#define TP   64               // pixels per block
#define SSTR 260              // s slice row stride (floats)
#define BK   32               // k-chunk per w stage
#define NCHUNK (KDIM/BK)      // 72
#define CPK  (256/BK)         // 8 chunks per kk slice
#define WSTR 36               // w smem row stride (floats)
#define WBUF (On*WSTR)        // 9216 floats per buffer
#define SBUF (TP*SSTR)        // 16640 floats per s buffer

// smem float offsets
#define S0_OFF   0
#define S1_OFF   (SBUF)                 // 16640
#define W0_OFF   (2*SBUF)               // 33280
#define W1_OFF   (W0_OFF + WBUF)        // 42496
#define CO_OFF   (W1_OFF + WBUF)        // 51712
#define SMEM_FLOATS (CO_OFF + 3*TP*KKn) // 53440
#define SMEM_BYTES (SMEM_FLOATS*4)      // 213760 B -> 1 block/SM

// ---------------- scratch ----------------
__device__ float g_xt[Bn*HWn*Cn];        // x transposed to NHWC
__device__ float g_py [Bn*KKn*HWn];
__device__ float g_px [Bn*KKn*HWn];
__device__ float g_msk[Bn*KKn*HWn];
__device__ float g_wsoff[Cn*KKn*28];
__device__ float g_wt2[On*KDIM];         // [o][kk*256+c]
__device__ float g_bnA[On];
__device__ float g_bnB[On];

// ---------------- f32x2 helpers ----------------
__device__ __forceinline__ ull pk2(float a, float b) {
    ull r; asm("mov.b64 %0, {%1, %2};" : "=l"(r) : "f"(a), "f"(b)); return r;
}
__device__ __forceinline__ void unpk(ull v, float& a, float& b) {
    asm("mov.b64 {%0, %1}, %2;" : "=f"(a), "=f"(b) : "l"(v));
}
__device__ __forceinline__ void fma2(ull& d, ull a, ull b) {
    asm("fma.rn.f32x2 %0, %1, %2, %0;" : "+l"(d) : "l"(a), "l"(b));
}
__device__ __forceinline__ uint32_t smem_u32(const void* p) {
    return (uint32_t)__cvta_generic_to_shared(p);
}
__device__ __forceinline__ void cp16(uint32_t dst, const void* src) {
    asm volatile("cp.async.cg.shared.global [%0], [%1], 16;" :: "r"(dst), "l"(src));
}
#define CP_COMMIT()  asm volatile("cp.async.commit_group;")
#define CP_WAIT(n)   asm volatile("cp.async.wait_group %0;" :: "n"(n))

// ---------------- prep ----------------
__global__ void prep_kernel(const float* __restrict__ w_off,
                            const float* __restrict__ w_dcn,
                            const float* __restrict__ b_dcn,
                            const float* __restrict__ gamma,
                            const float* __restrict__ beta,
                            const float* __restrict__ rmean,
                            const float* __restrict__ rvar) {
    int t = blockIdx.x * blockDim.x + threadIdx.x;
    int stride = gridDim.x * blockDim.x;
    for (int i = t; i < Cn*KKn*28; i += stride) {
        int oc = i % 28; int rest = i / 28;
        int kk = rest % KKn; int c = rest / KKn;
        g_wsoff[i] = (oc < 27) ? w_off[(oc*Cn + c)*KKn + kk] : 0.f;
    }
    for (int i = t; i < On*KDIM; i += stride) {
        int K = i % KDIM; int o = i / KDIM;
        int kk = K / Cn;  int c = K % Cn;
        g_wt2[i] = w_dcn[(o*Cn + c)*KKn + kk];
    }
    if (t < On) {
        float inv = rsqrtf(rvar[t] + 1e-5f);
        float A = gamma[t] * inv;
        g_bnA[t] = A;
        g_bnB[t] = (b_dcn[t] - rmean[t]) * A + beta[t];
    }
}

// ---------------- NCHW -> NHWC transpose ----------------
__global__ void transpose_kernel(const float* __restrict__ x) {
    __shared__ float tile[32][33];
    int bh = blockIdx.z;
    int c0 = blockIdx.y * 32;
    int w0 = blockIdx.x * 32;
    int b = bh / Hn; int h = bh % Hn;
    for (int i = threadIdx.y; i < 32; i += 8)
        tile[i][threadIdx.x] = x[((b*Cn + c0 + i)*Hn + h)*Wn + w0 + threadIdx.x];
    __syncthreads();
    for (int i = threadIdx.y; i < 32; i += 8)
        g_xt[((size_t)(b*Hn + h)*Wn + w0 + i)*Cn + c0 + threadIdx.x] = tile[threadIdx.x][i];
}

// ---------------- offset conv ----------------
__global__ __launch_bounds__(128) void offset_kernel(const float* __restrict__ x,
                                                     const float* __restrict__ b_off) {
    __shared__ float ws[32*KKn*28];
    int pix = blockIdx.x * 128 + threadIdx.x;
    int b = pix / HWn; int hw = pix % HWn;
    int h = hw / Wn;   int w = hw % Wn;

    ull acc[14];
    #pragma unroll
    for (int q = 0; q < 14; q++) acc[q] = 0ull;

    for (int c0 = 0; c0 < Cn; c0 += 32) {
        __syncthreads();
        for (int i = threadIdx.x; i < 32*KKn*28; i += 128)
            ws[i] = g_wsoff[c0*KKn*28 + i];
        __syncthreads();
        for (int c = 0; c < 32; c++) {
            const float* xr = x + ((size_t)(b*Cn + c0 + c)*Hn)*Wn;
            #pragma unroll
            for (int kk = 0; kk < 9; kk++) {
                int dy = kk/3 - 1, dx = kk%3 - 1;
                int yy = h + dy, xx = w + dx;
                float xv = 0.f;
                if ((unsigned)yy < (unsigned)Hn && (unsigned)xx < (unsigned)Wn)
                    xv = xr[yy*Wn + xx];
                ull xv2 = pk2(xv, xv);
                const ulonglong2* wrow = (const ulonglong2*)(ws + (c*KKn + kk)*28);
                #pragma unroll
                for (int q = 0; q < 7; q++) {
                    ulonglong2 wv = wrow[q];
                    fma2(acc[2*q],   wv.x, xv2);
                    fma2(acc[2*q+1], wv.y, xv2);
                }
            }
        }
    }

    float v[28];
    #pragma unroll
    for (int q = 0; q < 14; q++) unpk(acc[q], v[2*q], v[2*q+1]);

    #pragma unroll
    for (int k = 0; k < 9; k++) {
        int dy = k/3 - 1, dx = k%3 - 1;
        float py = v[2*k]   + b_off[2*k]   + (float)(h + dy);
        float px = v[2*k+1] + b_off[2*k+1] + (float)(w + dx);
        float mv = v[18+k] + b_off[18+k];
        float mm = 1.f / (1.f + expf(-mv));
        int idx = (b*KKn + k)*HWn + hw;
        g_py[idx] = py; g_px[idx] = px; g_msk[idx] = mm;
    }
}

// ---------------- main ----------------
__device__ __forceinline__ float4 corner_ld(const float* __restrict__ xtb, int y, int x, int c4) {
    if ((unsigned)y < (unsigned)Hn && (unsigned)x < (unsigned)Wn)
        return *(const float4*)(xtb + ((y*Wn + x) << 8) + (c4 << 2));
    return make_float4(0.f, 0.f, 0.f, 0.f);
}

__global__ __launch_bounds__(NT, 1) void main_kernel(float* __restrict__ out) {
    extern __shared__ float smem[];
    float* sbuf[2] = { smem + S0_OFF, smem + S1_OFF };
    float* w0  = smem + W0_OFF;
    float* w1  = smem + W1_OFF;
    float* spy = smem + CO_OFF;
    float* spx = spy + TP*KKn;
    float* smk = spx + TP*KKn;

    int tid  = threadIdx.x;
    int pixb = blockIdx.x * TP;
    int b    = pixb / HWn;
    int hwb  = pixb % HWn;

    // ---- w prefetch geometry: 512 thr, chunk = 256 rows x 8 quads = 2048 cp16
    int s_row  = tid >> 1;               // 0..255
    int s_half = (tid & 1) * 16;         // float offset 0 or 16
    const float* s_gsrc = g_wt2 + (size_t)s_row * KDIM + s_half;
    uint32_t s_d0 = smem_u32(w0 + s_row*WSTR + s_half);
    uint32_t s_d1 = smem_u32(w1 + s_row*WSTR + s_half);

    // prefetch chunks 0,1
    #pragma unroll
    for (int j = 0; j < 4; j++)
        cp16(s_d0 + j*16, s_gsrc + j*4);
    CP_COMMIT();
    #pragma unroll
    for (int j = 0; j < 4; j++)
        cp16(s_d1 + j*16, s_gsrc + j*4 + BK);
    CP_COMMIT();

    // ---- coords ----
    for (int i = tid; i < TP*KKn; i += NT) {
        int p = i / KKn, k = i % KKn;
        int gi = (b*KKn + k)*HWn + hwb + p;
        spy[i] = g_py[gi]; spx[i] = g_px[gi]; smk[i] = g_msk[gi];
    }
    __syncthreads();

    const float* xtb = g_xt + (size_t)b * (HWn*Cn);

    // ---- produce slice 0 fully ----
    #pragma unroll 1
    for (int cc = 0; cc < CPK; cc++) {
        int t  = cc*NT + tid;
        int c4 = t & 63;
        int p  = t >> 6;
        float py = spy[p*KKn + 0], px = spx[p*KKn + 0], mm = smk[p*KKn + 0];
        float fy = floorf(py), fx = floorf(px);
        int y0 = (int)fy, x0 = (int)fx;
        float wy = py - fy, wx = px - fx;
        float4 v00 = corner_ld(xtb, y0,   x0,   c4);
        float4 v01 = corner_ld(xtb, y0,   x0+1, c4);
        float4 v10 = corner_ld(xtb, y0+1, x0,   c4);
        float4 v11 = corner_ld(xtb, y0+1, x0+1, c4);
        float w00 = (1.f-wy)*(1.f-wx), w01 = (1.f-wy)*wx;
        float w10 = wy*(1.f-wx),       w11 = wy*wx;
        float4 r;
        r.x = (v00.x*w00 + v01.x*w01 + v10.x*w10 + v11.x*w11) * mm;
        r.y = (v00.y*w00 + v01.y*w01 + v10.y*w10 + v11.y*w11) * mm;
        r.z = (v00.z*w00 + v01.z*w01 + v10.z*w10 + v11.z*w11) * mm;
        r.w = (v00.w*w00 + v01.w*w01 + v10.w*w10 + v11.w*w11) * mm;
        *(float4*)(sbuf[0] + p*SSTR + c4*4) = r;
    }

    int og = tid >> 4;        // 0..31 -> o = og + 32*j
    int pg = tid & 15;        // 0..15 -> p = pg + 16*i

    ull acc[8][4];
    #pragma unroll
    for (int j = 0; j < 8; j++)
        #pragma unroll
        for (int i = 0; i < 4; i++) acc[j][i] = 0ull;

    int q = 0;  // global w chunk index (0..71)
    #pragma unroll 1
    for (int kk = 0; kk < KKn; kk++) {
        float* scur = sbuf[kk & 1];
        float* snxt = sbuf[(kk + 1) & 1];
        bool doprod = (kk + 1 < KKn);

        #pragma unroll 1
        for (int cc = 0; cc < CPK; cc++) {
            // ---- producer pre-issue: 4 corner LDGs for slice kk+1, task cc ----
            float4 v00, v01, v10, v11;
            float w00, w01, w10, w11, mm;
            int pp = 0, pc4 = 0;
            if (doprod) {
                int t  = cc*NT + tid;
                pc4 = t & 63;
                pp  = t >> 6;
                float py = spy[pp*KKn + kk+1], px = spx[pp*KKn + kk+1];
                mm = smk[pp*KKn + kk+1];
                float fy = floorf(py), fx = floorf(px);
                int y0 = (int)fy, x0 = (int)fx;
                float wy = py - fy, wx = px - fx;
                v00 = corner_ld(xtb, y0,   x0,   pc4);
                v01 = corner_ld(xtb, y0,   x0+1, pc4);
                v10 = corner_ld(xtb, y0+1, x0,   pc4);
                v11 = corner_ld(xtb, y0+1, x0+1, pc4);
                w00 = (1.f-wy)*(1.f-wx); w01 = (1.f-wy)*wx;
                w10 = wy*(1.f-wx);       w11 = wy*wx;
            }

            if (q < NCHUNK-1) { CP_WAIT(1); } else { CP_WAIT(0); }
            __syncthreads();   // w chunk q + (on cc==0) slice kk visible

            // ---- producer finish: interp + STS (corners die here) ----
            if (doprod) {
                float4 r;
                r.x = (v00.x*w00 + v01.x*w01 + v10.x*w10 + v11.x*w11) * mm;
                r.y = (v00.y*w00 + v01.y*w01 + v10.y*w10 + v11.y*w11) * mm;
                r.z = (v00.z*w00 + v01.z*w01 + v10.z*w10 + v11.z*w11) * mm;
                r.w = (v00.w*w00 + v01.w*w01 + v10.w*w10 + v11.w*w11) * mm;
                *(float4*)(snxt + pp*SSTR + pc4*4) = r;
            }

            // ---- FMA chunk ----
            const float* wb = (q & 1) ? w1 : w0;
            const float* sp = scur + pg*SSTR + cc*BK;

            #pragma unroll
            for (int kq = 0; kq < BK/4; kq++) {
                ulonglong2 sv0 = *(const ulonglong2*)(sp + 0*16*SSTR + kq*4);
                ulonglong2 sv1 = *(const ulonglong2*)(sp + 1*16*SSTR + kq*4);
                ulonglong2 sv2 = *(const ulonglong2*)(sp + 2*16*SSTR + kq*4);
                ulonglong2 sv3 = *(const ulonglong2*)(sp + 3*16*SSTR + kq*4);
                #pragma unroll
                for (int j = 0; j < 8; j++) {
                    ulonglong2 wv = *(const ulonglong2*)(wb + (og + 32*j)*WSTR + kq*4);
                    fma2(acc[j][0], wv.x, sv0.x);
                    fma2(acc[j][0], wv.y, sv0.y);
                    fma2(acc[j][1], wv.x, sv1.x);
                    fma2(acc[j][1], wv.y, sv1.y);
                    fma2(acc[j][2], wv.x, sv2.x);
                    fma2(acc[j][2], wv.y, sv2.y);
                    fma2(acc[j][3], wv.x, sv3.x);
                    fma2(acc[j][3], wv.y, sv3.y);
                }
            }
            __syncthreads();   // all warps done reading w chunk q (and s slice on cc==7)

            // prefetch chunk q+2 into the freed buffer
            if (q + 2 < NCHUNK) {
                uint32_t dst = (q & 1) ? s_d1 : s_d0;
                const float* gs = s_gsrc + (size_t)(q+2)*BK;
                #pragma unroll
                for (int j = 0; j < 4; j++)
                    cp16(dst + j*16, gs + j*4);
                CP_COMMIT();
            }
            q++;
        }
    }

    // ---- epilogue: BN + ReLU ----
    #pragma unroll
    for (int j = 0; j < 8; j++) {
        int o = og + 32*j;
        float A = g_bnA[o], Bb = g_bnB[o];
        float* orow = out + (size_t)(b*On + o)*HWn + hwb;
        #pragma unroll
        for (int i = 0; i < 4; i++) {
            float lo, hi; unpk(acc[j][i], lo, hi);
            float r = (lo + hi) * A + Bb;
            orow[pg + 16*i] = fmaxf(r, 0.f);
        }
    }
}

// ---------------- launch ----------------
extern "C" void kernel_launch(void* const* d_in, const int* in_sizes, int n_in,
                              void* d_out, int out_size) {
    const float* x      = (const float*)d_in[0];
    const float* w_off  = (const float*)d_in[1];
    const float* b_off  = (const float*)d_in[2];
    const float* w_dcn  = (const float*)d_in[3];
    const float* b_dcn  = (const float*)d_in[4];
    const float* gamma  = (const float*)d_in[5];
    const float* beta   = (const float*)d_in[6];
    const float* rmean  = (const float*)d_in[7];
    const float* rvar   = (const float*)d_in[8];
    float* out = (float*)d_out;

    cudaFuncSetAttribute(main_kernel, cudaFuncAttributeMaxDynamicSharedMemorySize, SMEM_BYTES);
    cudaFuncSetAttribute(main_kernel, cudaFuncAttributePreferredSharedMemoryCarveout, 100);

    prep_kernel<<<256, 256>>>(w_off, w_dcn, b_dcn, gamma, beta, rmean, rvar);

    dim3 tgrid(Wn/32, Cn/32, Bn*Hn);
    transpose_kernel<<<tgrid, dim3(32, 8)>>>(x);

    offset_kernel<<<(Bn*HWn)/128, 128>>>(x, b_off);

    main_kernel<<<(Bn*HWn)/TP, NT, SMEM_BYTES>>>(out);
}

// round 6
// speedup vs baseline: 1.3018x; 1.3018x over previous
#include <cuda_runtime.h>
#include <cstdint>

typedef unsigned long long ull;

#define KKn  9
#define Bn   8
#define Cn   256
#define Hn   96
#define Wn   96
#define On   256
#define HWn  (Hn*Wn)          // 9216
#define KDIM (Cn*KKn)         // 2304

// ---- main kernel tiling ----
#define NT   256              // threads per block
#define TP   32               // pixels per block
#define SSTR 260              // s slice row stride (floats)
#define BK   32               // k-chunk per w stage
#define NCHUNK (KDIM/BK)      // 72
#define CPK  (256/BK)         // 8 chunks per kk slice
#define WSTR 36               // w smem row stride (floats)
#define WBUF (On*WSTR)        // 9216 floats per buffer

// smem float offsets
#define S_OFF    0
#define W0_OFF   (TP*SSTR)            // 8320
#define W1_OFF   (W0_OFF + WBUF)      // 17536
#define CO_OFF   (W1_OFF + WBUF)      // 26752
#define SMEM_FLOATS (CO_OFF + 3*TP*KKn)
#define SMEM_BYTES (SMEM_FLOATS*4)    // 110,464 B -> 2 blocks/SM

// ---------------- scratch ----------------
__device__ float g_xt[Bn*HWn*Cn];        // x transposed to NHWC
__device__ float g_py [Bn*KKn*HWn];
__device__ float g_px [Bn*KKn*HWn];
__device__ float g_msk[Bn*KKn*HWn];
__device__ float g_wsoff[Cn*KKn*28];
__device__ float g_wt2[On*KDIM];         // [o][kk*256+c]
__device__ float g_bnA[On];
__device__ float g_bnB[On];

// ---------------- f32x2 helpers ----------------
__device__ __forceinline__ ull pk2(float a, float b) {
    ull r; asm("mov.b64 %0, {%1, %2};" : "=l"(r) : "f"(a), "f"(b)); return r;
}
__device__ __forceinline__ void unpk(ull v, float& a, float& b) {
    asm("mov.b64 {%0, %1}, %2;" : "=f"(a), "=f"(b) : "l"(v));
}
__device__ __forceinline__ void fma2(ull& d, ull a, ull b) {
    asm("fma.rn.f32x2 %0, %1, %2, %0;" : "+l"(d) : "l"(a), "l"(b));
}
__device__ __forceinline__ uint32_t smem_u32(const void* p) {
    return (uint32_t)__cvta_generic_to_shared(p);
}
__device__ __forceinline__ void cp16(uint32_t dst, const void* src) {
    asm volatile("cp.async.cg.shared.global [%0], [%1], 16;" :: "r"(dst), "l"(src));
}
#define CP_COMMIT()  asm volatile("cp.async.commit_group;")
#define CP_WAIT(n)   asm volatile("cp.async.wait_group %0;" :: "n"(n))

// ---------------- prep ----------------
__global__ void prep_kernel(const float* __restrict__ w_off,
                            const float* __restrict__ w_dcn,
                            const float* __restrict__ b_dcn,
                            const float* __restrict__ gamma,
                            const float* __restrict__ beta,
                            const float* __restrict__ rmean,
                            const float* __restrict__ rvar) {
    int t = blockIdx.x * blockDim.x + threadIdx.x;
    int stride = gridDim.x * blockDim.x;
    for (int i = t; i < Cn*KKn*28; i += stride) {
        int oc = i % 28; int rest = i / 28;
        int kk = rest % KKn; int c = rest / KKn;
        g_wsoff[i] = (oc < 27) ? w_off[(oc*Cn + c)*KKn + kk] : 0.f;
    }
    for (int i = t; i < On*KDIM; i += stride) {
        int K = i % KDIM; int o = i / KDIM;
        int kk = K / Cn;  int c = K % Cn;
        g_wt2[i] = w_dcn[(o*Cn + c)*KKn + kk];
    }
    if (t < On) {
        float inv = rsqrtf(rvar[t] + 1e-5f);
        float A = gamma[t] * inv;
        g_bnA[t] = A;
        g_bnB[t] = (b_dcn[t] - rmean[t]) * A + beta[t];
    }
}

// ---------------- NCHW -> NHWC transpose ----------------
__global__ void transpose_kernel(const float* __restrict__ x) {
    __shared__ float tile[32][33];
    int bh = blockIdx.z;
    int c0 = blockIdx.y * 32;
    int w0 = blockIdx.x * 32;
    int b = bh / Hn; int h = bh % Hn;
    for (int i = threadIdx.y; i < 32; i += 8)
        tile[i][threadIdx.x] = x[((b*Cn + c0 + i)*Hn + h)*Wn + w0 + threadIdx.x];
    __syncthreads();
    for (int i = threadIdx.y; i < 32; i += 8)
        g_xt[((size_t)(b*Hn + h)*Wn + w0 + i)*Cn + c0 + threadIdx.x] = tile[threadIdx.x][i];
}

// ---------------- offset conv ----------------
__global__ __launch_bounds__(128) void offset_kernel(const float* __restrict__ x,
                                                     const float* __restrict__ b_off) {
    __shared__ float ws[32*KKn*28];
    int pix = blockIdx.x * 128 + threadIdx.x;
    int b = pix / HWn; int hw = pix % HWn;
    int h = hw / Wn;   int w = hw % Wn;

    ull acc[14];
    #pragma unroll
    for (int q = 0; q < 14; q++) acc[q] = 0ull;

    for (int c0 = 0; c0 < Cn; c0 += 32) {
        __syncthreads();
        for (int i = threadIdx.x; i < 32*KKn*28; i += 128)
            ws[i] = g_wsoff[c0*KKn*28 + i];
        __syncthreads();
        for (int c = 0; c < 32; c++) {
            const float* xr = x + ((size_t)(b*Cn + c0 + c)*Hn)*Wn;
            #pragma unroll
            for (int kk = 0; kk < 9; kk++) {
                int dy = kk/3 - 1, dx = kk%3 - 1;
                int yy = h + dy, xx = w + dx;
                float xv = 0.f;
                if ((unsigned)yy < (unsigned)Hn && (unsigned)xx < (unsigned)Wn)
                    xv = xr[yy*Wn + xx];
                ull xv2 = pk2(xv, xv);
                const ulonglong2* wrow = (const ulonglong2*)(ws + (c*KKn + kk)*28);
                #pragma unroll
                for (int q = 0; q < 7; q++) {
                    ulonglong2 wv = wrow[q];
                    fma2(acc[2*q],   wv.x, xv2);
                    fma2(acc[2*q+1], wv.y, xv2);
                }
            }
        }
    }

    float v[28];
    #pragma unroll
    for (int q = 0; q < 14; q++) unpk(acc[q], v[2*q], v[2*q+1]);

    #pragma unroll
    for (int k = 0; k < 9; k++) {
        int dy = k/3 - 1, dx = k%3 - 1;
        float py = v[2*k]   + b_off[2*k]   + (float)(h + dy);
        float px = v[2*k+1] + b_off[2*k+1] + (float)(w + dx);
        float mv = v[18+k] + b_off[18+k];
        float mm = 1.f / (1.f + expf(-mv));
        int idx = (b*KKn + k)*HWn + hw;
        g_py[idx] = py; g_px[idx] = px; g_msk[idx] = mm;
    }
}

// ---------------- main ----------------
__device__ __forceinline__ float4 corner_ld(const float* __restrict__ xtb, int y, int x, int c4) {
    if ((unsigned)y < (unsigned)Hn && (unsigned)x < (unsigned)Wn)
        return *(const float4*)(xtb + ((y*Wn + x) << 8) + (c4 << 2));
    return make_float4(0.f, 0.f, 0.f, 0.f);
}

__global__ __launch_bounds__(NT, 2) void main_kernel(float* __restrict__ out) {
    extern __shared__ float smem[];
    float* s   = smem + S_OFF;          // [TP][SSTR] current kk slice
    float* w0  = smem + W0_OFF;
    float* w1  = smem + W1_OFF;
    float* spy = smem + CO_OFF;
    float* spx = spy + TP*KKn;
    float* smk = spx + TP*KKn;

    int tid  = threadIdx.x;
    int pixb = blockIdx.x * TP;
    int b    = pixb / HWn;
    int hwb  = pixb % HWn;

    // w prefetch geometry: oo = tid>>3 (row base 0..31), kq = tid&7 (16B quads)
    int s_oo = tid >> 3;
    int s_kq = tid & 7;
    const float* s_gsrc = g_wt2 + (size_t)s_oo * KDIM + s_kq*4;
    uint32_t s_d0 = smem_u32(w0 + s_oo*WSTR + s_kq*4);
    uint32_t s_d1 = smem_u32(w1 + s_oo*WSTR + s_kq*4);

    // prefetch chunk 0 only (distance-1 pipeline; cp(q+1) issued inside loop)
    #pragma unroll
    for (int j = 0; j < 8; j++)
        cp16(s_d0 + j*32*WSTR*4, s_gsrc + (size_t)j*32*KDIM);
    CP_COMMIT();

    for (int i = tid; i < TP*KKn; i += NT) {
        int p = i / KKn, k = i % KKn;
        int gi = (b*KKn + k)*HWn + hwb + p;
        spy[i] = g_py[gi]; spx[i] = g_px[gi]; smk[i] = g_msk[gi];
    }
    __syncthreads();   // coords visible

    const float* xtb = g_xt + (size_t)b * (HWn*Cn);

    int og = tid >> 3;        // 0..31 -> o = og + 32*j
    int pg = tid & 7;         // 0..7  -> p = pg + 8*i

    ull acc[8][4];
    #pragma unroll
    for (int j = 0; j < 8; j++)
        #pragma unroll
        for (int i = 0; i < 4; i++) acc[j][i] = 0ull;

    int q = 0;  // global w chunk index (0..71)
    #pragma unroll 1
    for (int kk = 0; kk < KKn; kk++) {
        // ---- produce s slice for this kk (2-task LDG batches for MLP) ----
        #pragma unroll 1
        for (int cc = 0; cc < CPK; cc += 2) {
            float4 A0[4], A1[4];
            float wy0, wx0, mm0, wy1, wx1, mm1;
            int p0, c40, p1, c41;
            {
                int t = cc*NT + tid;
                c40 = t & 63; p0 = t >> 6;
                float py = spy[p0*KKn + kk], px = spx[p0*KKn + kk];
                mm0 = smk[p0*KKn + kk];
                float fy = floorf(py), fx = floorf(px);
                int y0 = (int)fy, x0 = (int)fx;
                wy0 = py - fy; wx0 = px - fx;
                A0[0] = corner_ld(xtb, y0,   x0,   c40);
                A0[1] = corner_ld(xtb, y0,   x0+1, c40);
                A0[2] = corner_ld(xtb, y0+1, x0,   c40);
                A0[3] = corner_ld(xtb, y0+1, x0+1, c40);
            }
            {
                int t = (cc+1)*NT + tid;
                c41 = t & 63; p1 = t >> 6;
                float py = spy[p1*KKn + kk], px = spx[p1*KKn + kk];
                mm1 = smk[p1*KKn + kk];
                float fy = floorf(py), fx = floorf(px);
                int y0 = (int)fy, x0 = (int)fx;
                wy1 = py - fy; wx1 = px - fx;
                A1[0] = corner_ld(xtb, y0,   x0,   c41);
                A1[1] = corner_ld(xtb, y0,   x0+1, c41);
                A1[2] = corner_ld(xtb, y0+1, x0,   c41);
                A1[3] = corner_ld(xtb, y0+1, x0+1, c41);
            }
            {
                float w00 = (1.f-wy0)*(1.f-wx0), w01 = (1.f-wy0)*wx0;
                float w10 = wy0*(1.f-wx0),       w11 = wy0*wx0;
                float4 r;
                r.x = (A0[0].x*w00 + A0[1].x*w01 + A0[2].x*w10 + A0[3].x*w11) * mm0;
                r.y = (A0[0].y*w00 + A0[1].y*w01 + A0[2].y*w10 + A0[3].y*w11) * mm0;
                r.z = (A0[0].z*w00 + A0[1].z*w01 + A0[2].z*w10 + A0[3].z*w11) * mm0;
                r.w = (A0[0].w*w00 + A0[1].w*w01 + A0[2].w*w10 + A0[3].w*w11) * mm0;
                *(float4*)(s + p0*SSTR + c40*4) = r;
            }
            {
                float w00 = (1.f-wy1)*(1.f-wx1), w01 = (1.f-wy1)*wx1;
                float w10 = wy1*(1.f-wx1),       w11 = wy1*wx1;
                float4 r;
                r.x = (A1[0].x*w00 + A1[1].x*w01 + A1[2].x*w10 + A1[3].x*w11) * mm1;
                r.y = (A1[0].y*w00 + A1[1].y*w01 + A1[2].y*w10 + A1[3].y*w11) * mm1;
                r.z = (A1[0].z*w00 + A1[1].z*w01 + A1[2].z*w10 + A1[3].z*w11) * mm1;
                r.w = (A1[0].w*w00 + A1[1].w*w01 + A1[2].w*w10 + A1[3].w*w11) * mm1;
                *(float4*)(s + p1*SSTR + c41*4) = r;
            }
        }

        // ---- consume CPK w chunks against this slice ----
        #pragma unroll 1
        for (int cc = 0; cc < CPK; cc++) {
            CP_WAIT(0);        // this thread's cp for chunk q complete
            __syncthreads();   // all threads' cp for chunk q visible; buffer (q-1)&1 free;
                               // (on cc==0) s slice kk visible

            // issue cp for chunk q+1 into buffer (q+1)&1 == (q-1)&1 (provably free)
            if (q + 1 < NCHUNK) {
                uint32_t dst = (q & 1) ? s_d0 : s_d1;
                const float* gs = s_gsrc + (size_t)(q+1)*BK;
                #pragma unroll
                for (int j = 0; j < 8; j++)
                    cp16(dst + j*32*WSTR*4, gs + (size_t)j*32*KDIM);
                CP_COMMIT();
            }

            const float* wb = (q & 1) ? w1 : w0;
            const float* sp = s + pg*SSTR + cc*BK;

            #pragma unroll
            for (int kq = 0; kq < BK/4; kq++) {
                ulonglong2 sv0 = *(const ulonglong2*)(sp + 0*8*SSTR + kq*4);
                ulonglong2 sv1 = *(const ulonglong2*)(sp + 1*8*SSTR + kq*4);
                ulonglong2 sv2 = *(const ulonglong2*)(sp + 2*8*SSTR + kq*4);
                ulonglong2 sv3 = *(const ulonglong2*)(sp + 3*8*SSTR + kq*4);
                #pragma unroll
                for (int j = 0; j < 8; j++) {
                    ulonglong2 wv = *(const ulonglong2*)(wb + (og + 32*j)*WSTR + kq*4);
                    fma2(acc[j][0], wv.x, sv0.x);
                    fma2(acc[j][0], wv.y, sv0.y);
                    fma2(acc[j][1], wv.x, sv1.x);
                    fma2(acc[j][1], wv.y, sv1.y);
                    fma2(acc[j][2], wv.x, sv2.x);
                    fma2(acc[j][2], wv.y, sv2.y);
                    fma2(acc[j][3], wv.x, sv3.x);
                    fma2(acc[j][3], wv.y, sv3.y);
                }
            }
            q++;
        }

        // slice boundary: all warps must finish reading s before next produce
        if (kk + 1 < KKn) __syncthreads();
    }

    // ---- epilogue: BN + ReLU ----
    #pragma unroll
    for (int j = 0; j < 8; j++) {
        int o = og + 32*j;
        float A = g_bnA[o], Bb = g_bnB[o];
        float* orow = out + (size_t)(b*On + o)*HWn + hwb;
        #pragma unroll
        for (int i = 0; i < 4; i++) {
            float lo, hi; unpk(acc[j][i], lo, hi);
            float r = (lo + hi) * A + Bb;
            orow[pg + 8*i] = fmaxf(r, 0.f);
        }
    }
}

// ---------------- launch ----------------
extern "C" void kernel_launch(void* const* d_in, const int* in_sizes, int n_in,
                              void* d_out, int out_size) {
    const float* x      = (const float*)d_in[0];
    const float* w_off  = (const float*)d_in[1];
    const float* b_off  = (const float*)d_in[2];
    const float* w_dcn  = (const float*)d_in[3];
    const float* b_dcn  = (const float*)d_in[4];
    const float* gamma  = (const float*)d_in[5];
    const float* beta   = (const float*)d_in[6];
    const float* rmean  = (const float*)d_in[7];
    const float* rvar   = (const float*)d_in[8];
    float* out = (float*)d_out;

    cudaFuncSetAttribute(main_kernel, cudaFuncAttributeMaxDynamicSharedMemorySize, SMEM_BYTES);
    cudaFuncSetAttribute(main_kernel, cudaFuncAttributePreferredSharedMemoryCarveout, 100);

    prep_kernel<<<256, 256>>>(w_off, w_dcn, b_dcn, gamma, beta, rmean, rvar);

    dim3 tgrid(Wn/32, Cn/32, Bn*Hn);
    transpose_kernel<<<tgrid, dim3(32, 8)>>>(x);

    offset_kernel<<<(Bn*HWn)/128, 128>>>(x, b_off);

    main_kernel<<<(Bn*HWn)/TP, NT, SMEM_BYTES>>>(out);
}